// round 15
// baseline (speedup 1.0000x reference)
#include <cuda_runtime.h>
#include <cuda_fp16.h>
#include <math.h>
#include <stdint.h>

#define N_NODES 100000
#define N_EDGES 1600000
#define F_IN    500
#define F_HID   64
#define F_OUT   40
#define CAP     128          // bucket capacity per node (P(deg>127) ~ 0)

// ---------------- scratch (static device globals; no allocations) ----------
__device__ __half2 g_xw1h[N_NODES * (F_HID / 2)];  // X @ W1, fp16 pairs
__device__ __half2 g_hh  [N_NODES * (F_HID / 2)];  // relu(conv1), fp16 pairs
__device__ __half2 g_xw2h[N_NODES * (F_OUT / 2)];  // h @ W2, fp16 pairs
__device__ float   g_dinv[N_NODES];
__device__ int     g_cnt [N_NODES];                // zero at entry (module init / re-zeroed)
__device__ int     g_col [N_NODES * CAP];          // src buckets

__device__ __forceinline__ uint32_t f2tf32(float x) {
    uint32_t r;
    asm("cvt.rna.tf32.f32 %0, %1;" : "=r"(r) : "f"(x));
    return r;
}

__device__ __forceinline__ void mma_tf32(float* c, const uint32_t* a, const uint32_t* b) {
    asm volatile(
        "mma.sync.aligned.m16n8k8.row.col.f32.tf32.tf32.f32 "
        "{%0,%1,%2,%3}, {%4,%5,%6,%7}, {%8,%9}, {%0,%1,%2,%3};"
        : "+f"(c[0]), "+f"(c[1]), "+f"(c[2]), "+f"(c[3])
        : "r"(a[0]), "r"(a[1]), "r"(a[2]), "r"(a[3]), "r"(b[0]), "r"(b[1]));
}

__device__ __forceinline__ void cp16(uint32_t smem_addr, const void* gptr, int src_bytes) {
    asm volatile("cp.async.cg.shared.global [%0], [%1], 16, %2;"
                 :: "r"(smem_addr), "l"(gptr), "r"(src_bytes));
}

// ------------- single-pass bucket fill (replaces deg+scan+fill) ------------
// edge_index is int32 (JAX downcasts int64 without x64 mode)
__global__ void k_fill(const int* __restrict__ ei, int E) {
    int i = blockIdx.x * blockDim.x + threadIdx.x;
    if (i < E) {
        int src = ei[i];
        int dst = ei[E + i];
        if (dst >= 0 && dst < N_NODES && src >= 0 && src < N_NODES) {
            int p = atomicAdd(&g_cnt[dst], 1);
            if (p < CAP) g_col[dst * CAP + p] = src;
        }
    }
}

__global__ void k_dinv(int n) {
    int i = blockIdx.x * blockDim.x + threadIdx.x;
    if (i < n) g_dinv[i] = rsqrtf((float)(g_cnt[i] + 1));   // +1 self loop
}

// ---------------- GEMM1 (tf32, cp.async 2-stage) ---------------------------
// X[M,500] @ W1[500,64] -> g_xw1h (fp16).  BM=128, BN=64, BK=32.
#define G1_BM 128
#define G1_BK 32
#define G1_SA 36    // As row stride (floats): conflict-free
#define G1_SB 72    // Bs row stride (floats): conflict-free
#define G1_A_STAGE (G1_BM * G1_SA)
#define G1_B_STAGE (G1_BK * G1_SB)
#define G1_SMEM_BYTES ((2 * G1_A_STAGE + 2 * G1_B_STAGE) * 4)

extern __shared__ float g1_smem[];

__global__ __launch_bounds__(256) void k_gemm1_tf32(const float* __restrict__ X,
                                                    const float* __restrict__ W1,
                                                    int M) {
    float* As = g1_smem;                       // [2][128][36]  (m,k)
    float* Bs = g1_smem + 2 * G1_A_STAGE;      // [2][32][72]   (k,n) raw W1 floats
    uint32_t as_u = (uint32_t)__cvta_generic_to_shared(As);
    uint32_t bs_u = (uint32_t)__cvta_generic_to_shared(Bs);

    int tid  = threadIdx.x;
    int lane = tid & 31, warp = tid >> 5;
    int warp_m = warp >> 1;
    int warp_n = warp & 1;
    int g  = lane >> 2;
    int tg = lane & 3;
    int row0 = blockIdx.x * G1_BM;

    float c[2][4][4] = {};

    auto load_stage = [&](int st, int k0) {
        #pragma unroll
        for (int i = 0; i < 4; i++) {
            int s  = tid + i * 256;
            int r  = s >> 3;
            int kq = s & 7;
            int k  = k0 + kq * 4;
            int grow = row0 + r;
            bool v = (grow < M) && (k < F_IN);      // 500 % 4 == 0
            const float* gp = X + (size_t)(v ? grow : 0) * F_IN + (v ? k : 0);
            cp16(as_u + (uint32_t)(((st * G1_BM + r) * G1_SA + kq * 4) * 4), gp, v ? 16 : 0);
        }
        #pragma unroll
        for (int i = 0; i < 2; i++) {
            int s  = tid + i * 256;
            int kr = s >> 4;
            int nq = s & 15;
            int k  = k0 + kr;
            bool v = (k < F_IN);
            const float* gp = W1 + (size_t)(v ? k : 0) * F_HID + nq * 4;
            cp16(bs_u + (uint32_t)(((st * G1_BK + kr) * G1_SB + nq * 4) * 4), gp, v ? 16 : 0);
        }
        asm volatile("cp.async.commit_group;");
    };

    load_stage(0, 0);

    #pragma unroll 1
    for (int it = 0; it < 16; it++) {
        if (it < 15) {
            load_stage((it + 1) & 1, (it + 1) * G1_BK);
            asm volatile("cp.async.wait_group 1;");
        } else {
            asm volatile("cp.async.wait_group 0;");
        }
        __syncthreads();

        const float* A = As + (it & 1) * G1_A_STAGE;
        const float* B = Bs + (it & 1) * G1_B_STAGE;
        int m0 = warp_m * 32;
        int n0 = warp_n * 32;
        #pragma unroll
        for (int kb = 0; kb < G1_BK; kb += 8) {
            uint32_t a[2][4], b[4][2];
            #pragma unroll
            for (int mf = 0; mf < 2; mf++) {
                int r = m0 + mf * 16 + g;
                a[mf][0] = f2tf32(A[r * G1_SA + kb + tg]);
                a[mf][1] = f2tf32(A[(r + 8) * G1_SA + kb + tg]);
                a[mf][2] = f2tf32(A[r * G1_SA + kb + tg + 4]);
                a[mf][3] = f2tf32(A[(r + 8) * G1_SA + kb + tg + 4]);
            }
            #pragma unroll
            for (int nf = 0; nf < 4; nf++) {
                int n = n0 + nf * 8 + g;
                b[nf][0] = f2tf32(B[(kb + tg) * G1_SB + n]);
                b[nf][1] = f2tf32(B[(kb + tg + 4) * G1_SB + n]);
            }
            #pragma unroll
            for (int mf = 0; mf < 2; mf++)
                #pragma unroll
                for (int nf = 0; nf < 4; nf++)
                    mma_tf32(c[mf][nf], a[mf], b[nf]);
        }
        __syncthreads();
    }

    #pragma unroll
    for (int mf = 0; mf < 2; mf++) {
        int r0 = row0 + warp_m * 32 + mf * 16 + g;
        int r1 = r0 + 8;
        #pragma unroll
        for (int nf = 0; nf < 4; nf++) {
            int col2 = (warp_n * 32 + nf * 8 + tg * 2) >> 1;
            if (r0 < M)
                g_xw1h[(size_t)r0 * (F_HID / 2) + col2] =
                    __floats2half2_rn(c[mf][nf][0], c[mf][nf][1]);
            if (r1 < M)
                g_xw1h[(size_t)r1 * (F_HID / 2) + col2] =
                    __floats2half2_rn(c[mf][nf][2], c[mf][nf][3]);
        }
    }
}

// ------- agg layer 1 (F=64) + bias + relu -> g_hh (pure gather) ------------
__global__ __launch_bounds__(256) void k_agg1(const float* __restrict__ b1, int N) {
    int lane = threadIdx.x & 31, warp = threadIdx.x >> 5;
    int n = blockIdx.x * 8 + warp;
    if (n >= N) return;
    float bx = b1[lane * 2], by = b1[lane * 2 + 1];

    int start = n * CAP;
    int end = start + min(g_cnt[n], CAP);
    float ax = 0.f, ay = 0.f;
    int e = start;
    for (; e + 4 <= end; e += 4) {
        int s0 = g_col[e],     s1 = g_col[e + 1];
        int s2 = g_col[e + 2], s3 = g_col[e + 3];
        float2 v0 = __half22float2(g_xw1h[(size_t)s0 * (F_HID / 2) + lane]);
        float2 v1 = __half22float2(g_xw1h[(size_t)s1 * (F_HID / 2) + lane]);
        float2 v2 = __half22float2(g_xw1h[(size_t)s2 * (F_HID / 2) + lane]);
        float2 v3 = __half22float2(g_xw1h[(size_t)s3 * (F_HID / 2) + lane]);
        float w0 = g_dinv[s0], w1 = g_dinv[s1];
        float w2 = g_dinv[s2], w3 = g_dinv[s3];
        ax += w0 * v0.x + w1 * v1.x + w2 * v2.x + w3 * v3.x;
        ay += w0 * v0.y + w1 * v1.y + w2 * v2.y + w3 * v3.y;
    }
    for (; e < end; e++) {
        int s = g_col[e];
        float2 v = __half22float2(g_xw1h[(size_t)s * (F_HID / 2) + lane]);
        float w = g_dinv[s];
        ax += w * v.x;
        ay += w * v.y;
    }
    float dn = g_dinv[n];
    float2 sv = __half22float2(g_xw1h[(size_t)n * (F_HID / 2) + lane]);
    float ox = fmaxf(dn * (ax + dn * sv.x) + bx, 0.f);
    float oy = fmaxf(dn * (ay + dn * sv.y) + by, 0.f);
    g_hh[(size_t)n * (F_HID / 2) + lane] = __floats2half2_rn(ox, oy);
}

// ---------------- GEMM2 (tf32 mma): g_hh[M,64] @ W2[64,40] -> g_xw2h -------
#define G2_SA 68   // h tile row stride (floats)

__global__ __launch_bounds__(128) void k_gemm2_tf32(const float* __restrict__ W2,
                                                    int M) {
    __shared__ float Af[128 * G2_SA];            // 34.8 KB
    __shared__ float W2s[F_HID * F_OUT];         // 10.2 KB (tf32 bits, k-major)
    int tid = threadIdx.x;
    int lane = tid & 31, warp = tid >> 5;
    int g  = lane >> 2;
    int tg = lane & 3;
    int row0 = blockIdx.x * 128;

    for (int i = tid; i < F_HID * F_OUT; i += 128)
        W2s[i] = __uint_as_float(f2tf32(W2[i]));

    #pragma unroll
    for (int i = 0; i < 8; i++) {
        int idx = tid + i * 128;
        int r = idx >> 3;
        int cq = idx & 7;
        int grow = row0 + r;
        float f[8];
        if (grow < M) {
            uint4 u = *(const uint4*)&g_hh[(size_t)grow * (F_HID / 2) + cq * 4];
            float2 p0 = __half22float2(*(__half2*)&u.x);
            float2 p1 = __half22float2(*(__half2*)&u.y);
            float2 p2 = __half22float2(*(__half2*)&u.z);
            float2 p3 = __half22float2(*(__half2*)&u.w);
            f[0]=p0.x; f[1]=p0.y; f[2]=p1.x; f[3]=p1.y;
            f[4]=p2.x; f[5]=p2.y; f[6]=p3.x; f[7]=p3.y;
        } else {
            #pragma unroll
            for (int j = 0; j < 8; j++) f[j] = 0.f;
        }
        #pragma unroll
        for (int j = 0; j < 8; j++) Af[r * G2_SA + cq * 8 + j] = f[j];
    }
    __syncthreads();

    float c[2][5][4] = {};
    int m0 = warp * 32;
    #pragma unroll
    for (int kb = 0; kb < F_HID; kb += 8) {
        uint32_t a[2][4], b[5][2];
        #pragma unroll
        for (int mf = 0; mf < 2; mf++) {
            int r = m0 + mf * 16 + g;
            a[mf][0] = __float_as_uint(Af[r * G2_SA + kb + tg]);
            a[mf][1] = __float_as_uint(Af[(r + 8) * G2_SA + kb + tg]);
            a[mf][2] = __float_as_uint(Af[r * G2_SA + kb + tg + 4]);
            a[mf][3] = __float_as_uint(Af[(r + 8) * G2_SA + kb + tg + 4]);
        }
        #pragma unroll
        for (int nf = 0; nf < 5; nf++) {
            int n = nf * 8 + g;
            b[nf][0] = __float_as_uint(W2s[(kb + tg) * F_OUT + n]);
            b[nf][1] = __float_as_uint(W2s[(kb + tg + 4) * F_OUT + n]);
        }
        #pragma unroll
        for (int mf = 0; mf < 2; mf++)
            #pragma unroll
            for (int nf = 0; nf < 5; nf++)
                mma_tf32(c[mf][nf], a[mf], b[nf]);
    }

    #pragma unroll
    for (int mf = 0; mf < 2; mf++) {
        int r0 = row0 + m0 + mf * 16 + g;
        int r1 = r0 + 8;
        #pragma unroll
        for (int nf = 0; nf < 5; nf++) {
            int col2 = (nf * 8 + tg * 2) >> 1;
            if (r0 < M)
                g_xw2h[(size_t)r0 * (F_OUT / 2) + col2] =
                    __floats2half2_rn(c[mf][nf][0], c[mf][nf][1]);
            if (r1 < M)
                g_xw2h[(size_t)r1 * (F_OUT / 2) + col2] =
                    __floats2half2_rn(c[mf][nf][2], c[mf][nf][3]);
        }
    }
}

// ------- agg layer 2 (F=40) + bias + fused log_softmax -> d_out ------------
// last consumer of g_cnt: resets it for the next replay.
__global__ __launch_bounds__(256) void k_agg2(const float* __restrict__ b2,
                                              float* __restrict__ out, int N,
                                              long long logits_off) {
    int warp = (blockIdx.x * blockDim.x + threadIdx.x) >> 5;
    int lane = threadIdx.x & 31;
    if (warp >= N) return;
    int n = warp;
    bool act = lane < 20;
    int start = n * CAP;
    int end = start + min(g_cnt[n], CAP);
    if (lane == 0) g_cnt[n] = 0;   // restore entry invariant for next replay

    float ax = 0.f, ay = 0.f;
    int e = start;
    for (; e + 4 <= end; e += 4) {
        int s0 = g_col[e],     s1 = g_col[e + 1];
        int s2 = g_col[e + 2], s3 = g_col[e + 3];
        if (act) {
            float2 v0 = __half22float2(g_xw2h[(size_t)s0 * (F_OUT / 2) + lane]);
            float2 v1 = __half22float2(g_xw2h[(size_t)s1 * (F_OUT / 2) + lane]);
            float2 v2 = __half22float2(g_xw2h[(size_t)s2 * (F_OUT / 2) + lane]);
            float2 v3 = __half22float2(g_xw2h[(size_t)s3 * (F_OUT / 2) + lane]);
            float w0 = g_dinv[s0], w1 = g_dinv[s1];
            float w2 = g_dinv[s2], w3 = g_dinv[s3];
            ax += w0 * v0.x + w1 * v1.x + w2 * v2.x + w3 * v3.x;
            ay += w0 * v0.y + w1 * v1.y + w2 * v2.y + w3 * v3.y;
        }
    }
    for (; e < end; e++) {
        int s = g_col[e];
        if (act) {
            float2 v = __half22float2(g_xw2h[(size_t)s * (F_OUT / 2) + lane]);
            float w = g_dinv[s];
            ax += w * v.x;
            ay += w * v.y;
        }
    }
    float dn = g_dinv[n];
    float o0 = 0.f, o1 = 0.f;
    if (act) {
        float2 sv = __half22float2(g_xw2h[(size_t)n * (F_OUT / 2) + lane]);
        o0 = dn * (ax + dn * sv.x) + b2[lane * 2];
        o1 = dn * (ay + dn * sv.y) + b2[lane * 2 + 1];
    }
    float m = act ? fmaxf(o0, o1) : -3.402823e38f;
    #pragma unroll
    for (int off = 16; off > 0; off >>= 1)
        m = fmaxf(m, __shfl_xor_sync(0xffffffffu, m, off));
    float s = act ? (expf(o0 - m) + expf(o1 - m)) : 0.f;
    #pragma unroll
    for (int off = 16; off > 0; off >>= 1)
        s += __shfl_xor_sync(0xffffffffu, s, off);
    float lse = logf(s) + m;
    if (act) {
        size_t base = (size_t)n * F_OUT + lane * 2;
        out[base]     = o0 - lse;
        out[base + 1] = o1 - lse;
        if (logits_off > 0) {
            out[(size_t)logits_off + base]     = o0;
            out[(size_t)logits_off + base + 1] = o1;
        }
    }
}

// ---------------------------------------------------------------------------
extern "C" void kernel_launch(void* const* d_in, const int* in_sizes, int n_in,
                              void* d_out, int out_size) {
    const float* x  = (const float*)d_in[0];
    const int*   ei = (const int*)d_in[1];     // int32 (JAX x64 disabled)
    const float* W1 = (const float*)d_in[2];
    const float* b1 = (const float*)d_in[3];
    const float* W2 = (const float*)d_in[4];
    const float* b2 = (const float*)d_in[5];
    float* out = (float*)d_out;

    int N = in_sizes[0] / F_IN;    // 100000
    int E = in_sizes[1] / 2;       // 1600000

    long long logits_off = ((long long)out_size >= 2LL * N * F_OUT)
                         ? (long long)N * F_OUT : 0;

    // not a stream op; idempotent and legal during graph capture
    cudaFuncSetAttribute(k_gemm1_tf32,
                         cudaFuncAttributeMaxDynamicSharedMemorySize,
                         G1_SMEM_BYTES);

    // single-pass bucket CSR (g_cnt == 0 at entry: module init / agg2 re-zero)
    k_fill<<<(E + 255) / 256, 256>>>(ei, E);
    k_dinv<<<(N + 255) / 256, 256>>>(N);

    // layer 1
    k_gemm1_tf32<<<(N + G1_BM - 1) / G1_BM, 256, G1_SMEM_BYTES>>>(x, W1, N);
    k_agg1<<<(N + 7) / 8, 256>>>(b1, N);

    // layer 2
    k_gemm2_tf32<<<(N + 127) / 128, 128>>>(W2, N);
    k_agg2<<<(N * 32 + 255) / 256, 256>>>(b2, out, N, logits_off);
}

// round 16
// speedup vs baseline: 1.7825x; 1.7825x over previous
#include <cuda_runtime.h>
#include <cuda_fp16.h>
#include <math.h>
#include <stdint.h>

#define N_NODES 100000
#define N_EDGES 1600000
#define F_IN    500
#define F_HID   64
#define F_OUT   40

// ---------------- scratch (static device globals; no allocations) ----------
// g_xw1h / g_xw2h hold dinv-PRESCALED transforms: xw'[r] = dinv[r] * (x @ W)[r]
__device__ __half2 g_xw1h[N_NODES * (F_HID / 2)];
__device__ __half2 g_hh  [N_NODES * (F_HID / 2)];  // relu(conv1), fp16 pairs
__device__ __half2 g_xw2h[N_NODES * (F_OUT / 2)];
__device__ float   g_w1t[F_IN * F_HID];            // W1 pre-converted to tf32 bits
__device__ float   g_dinv[N_NODES];
__device__ int     g_deg [N_NODES];                // zero at entry (module init / re-zeroed)
__device__ int     g_cnt [N_NODES];
__device__ int     g_rowptr[N_NODES + 1];
__device__ int     g_col[N_EDGES];                 // src per CSR slot
__device__ int     g_blocksum[128];

__device__ __forceinline__ uint32_t f2tf32(float x) {
    uint32_t r;
    asm("cvt.rna.tf32.f32 %0, %1;" : "=r"(r) : "f"(x));
    return r;
}

__device__ __forceinline__ int warp_incl_scan(int v, int lane) {
    #pragma unroll
    for (int off = 1; off < 32; off <<= 1) {
        int t = __shfl_up_sync(0xffffffffu, v, off);
        if (lane >= off) v += t;
    }
    return v;
}

__device__ __forceinline__ void mma_tf32(float* c, const uint32_t* a, const uint32_t* b) {
    asm volatile(
        "mma.sync.aligned.m16n8k8.row.col.f32.tf32.tf32.f32 "
        "{%0,%1,%2,%3}, {%4,%5,%6,%7}, {%8,%9}, {%0,%1,%2,%3};"
        : "+f"(c[0]), "+f"(c[1]), "+f"(c[2]), "+f"(c[3])
        : "r"(a[0]), "r"(a[1]), "r"(a[2]), "r"(a[3]), "r"(b[0]), "r"(b[1]));
}

__device__ __forceinline__ void cp16(uint32_t smem_addr, const void* gptr, int src_bytes) {
    asm volatile("cp.async.cg.shared.global [%0], [%1], 16, %2;"
                 :: "r"(smem_addr), "l"(gptr), "r"(src_bytes));
}

// ------------- deg histogram + fused W1->tf32 conversion -------------------
// edge_index is int32 (JAX downcasts int64 without x64 mode)
__global__ void k_deg(const int* __restrict__ ei, const float* __restrict__ W1, int E) {
    int i = blockIdx.x * blockDim.x + threadIdx.x;
    if (i < F_IN * F_HID) g_w1t[i] = __uint_as_float(f2tf32(W1[i]));
    if (i < E) {
        int dst = ei[E + i];
        if (dst >= 0 && dst < N_NODES) atomicAdd(&g_deg[dst], 1);
    }
}

// block-local exclusive scan of g_deg into g_rowptr (+ fused dinv)
__global__ void k_scan_blocks(int n) {
    __shared__ int wsum[32];
    int tid = threadIdx.x;
    int lane = tid & 31, warp = tid >> 5;
    int gid = blockIdx.x * 1024 + tid;
    int v = (gid < n) ? g_deg[gid] : 0;
    if (gid < n) g_dinv[gid] = rsqrtf((float)(v + 1));   // +1 self loop
    int incl = warp_incl_scan(v, lane);
    if (lane == 31) wsum[warp] = incl;
    __syncthreads();
    if (warp == 0) {
        int s = wsum[lane];
        s = warp_incl_scan(s, lane);
        wsum[lane] = s;
    }
    __syncthreads();
    int woff = (warp > 0) ? wsum[warp - 1] : 0;
    if (gid < n) g_rowptr[gid] = woff + incl - v;        // exclusive
    if (tid == 1023) g_blocksum[blockIdx.x] = woff + incl;
}

// every block redundantly scans the (<=128) block sums, applies its offset,
// and seeds g_cnt with the final rowptr (cursor for fill).
__global__ void k_scan_add(int n, int E, int nb) {
    __shared__ int bexc[128];
    __shared__ int wsum[4];
    int tid = threadIdx.x;
    int lane = tid & 31, warp = tid >> 5;
    if (tid < 128) {
        int v = (tid < nb) ? g_blocksum[tid] : 0;
        int incl = warp_incl_scan(v, lane);
        if (lane == 31) wsum[warp] = incl;
        bexc[tid] = incl - v;
    }
    __syncthreads();
    if (tid == 0) {
        int a = 0;
        #pragma unroll
        for (int w = 0; w < 4; w++) { int t = wsum[w]; wsum[w] = a; a += t; }
    }
    __syncthreads();
    int gid = blockIdx.x * 1024 + tid;
    if (gid < n) {
        int off = bexc[blockIdx.x] + wsum[blockIdx.x >> 5];
        int p = g_rowptr[gid] + off;
        g_rowptr[gid] = p;
        g_cnt[gid] = p;
    }
    if (gid == 0) g_rowptr[n] = E;
}

// fill CSR columns (packed, 4-byte payload)
__global__ void k_fill_col(const int* __restrict__ ei, int E) {
    int i = blockIdx.x * blockDim.x + threadIdx.x;
    if (i < E) {
        int src = ei[i];
        int dst = ei[E + i];
        if (dst >= 0 && dst < N_NODES && src >= 0 && src < N_NODES) {
            int p = atomicAdd(&g_cnt[dst], 1);
            g_col[p] = src;
        }
    }
}

// ---------------- GEMM1 (tf32, cp.async 2-stage) ---------------------------
// X[M,500] @ W1t[500,64] -> g_xw1h = dinv * (X@W1), fp16.
#define G1_BM 128
#define G1_BK 32
#define G1_SA 36    // As row stride (floats): conflict-free
#define G1_SB 72    // Bs row stride (floats): conflict-free
#define G1_A_STAGE (G1_BM * G1_SA)
#define G1_B_STAGE (G1_BK * G1_SB)
#define G1_SMEM_BYTES ((2 * G1_A_STAGE + 2 * G1_B_STAGE) * 4)

extern __shared__ float g1_smem[];

__global__ __launch_bounds__(256) void k_gemm1_tf32(const float* __restrict__ X,
                                                    int M) {
    float* As = g1_smem;                       // [2][128][36]  (m,k)
    float* Bs = g1_smem + 2 * G1_A_STAGE;      // [2][32][72]   (k,n)
    uint32_t as_u = (uint32_t)__cvta_generic_to_shared(As);
    uint32_t bs_u = (uint32_t)__cvta_generic_to_shared(Bs);

    int tid  = threadIdx.x;
    int lane = tid & 31, warp = tid >> 5;
    int warp_m = warp >> 1;
    int warp_n = warp & 1;
    int g  = lane >> 2;
    int tg = lane & 3;
    int row0 = blockIdx.x * G1_BM;

    float c[2][4][4] = {};

    auto load_stage = [&](int st, int k0) {
        #pragma unroll
        for (int i = 0; i < 4; i++) {
            int s  = tid + i * 256;
            int r  = s >> 3;
            int kq = s & 7;
            int k  = k0 + kq * 4;
            int grow = row0 + r;
            bool v = (grow < M) && (k < F_IN);      // 500 % 4 == 0
            const float* gp = X + (size_t)(v ? grow : 0) * F_IN + (v ? k : 0);
            cp16(as_u + (uint32_t)(((st * G1_BM + r) * G1_SA + kq * 4) * 4), gp, v ? 16 : 0);
        }
        #pragma unroll
        for (int i = 0; i < 2; i++) {
            int s  = tid + i * 256;
            int kr = s >> 4;
            int nq = s & 15;
            int k  = k0 + kr;
            bool v = (k < F_IN);
            const float* gp = g_w1t + (size_t)(v ? k : 0) * F_HID + nq * 4;
            cp16(bs_u + (uint32_t)(((st * G1_BK + kr) * G1_SB + nq * 4) * 4), gp, v ? 16 : 0);
        }
        asm volatile("cp.async.commit_group;");
    };

    load_stage(0, 0);

    #pragma unroll 1
    for (int it = 0; it < 16; it++) {
        if (it < 15) {
            load_stage((it + 1) & 1, (it + 1) * G1_BK);
            asm volatile("cp.async.wait_group 1;");
        } else {
            asm volatile("cp.async.wait_group 0;");
        }
        __syncthreads();

        const float* A = As + (it & 1) * G1_A_STAGE;
        const float* B = Bs + (it & 1) * G1_B_STAGE;
        int m0 = warp_m * 32;
        int n0 = warp_n * 32;
        #pragma unroll
        for (int kb = 0; kb < G1_BK; kb += 8) {
            uint32_t a[2][4], b[4][2];
            #pragma unroll
            for (int mf = 0; mf < 2; mf++) {
                int r = m0 + mf * 16 + g;
                a[mf][0] = f2tf32(A[r * G1_SA + kb + tg]);
                a[mf][1] = f2tf32(A[(r + 8) * G1_SA + kb + tg]);
                a[mf][2] = f2tf32(A[r * G1_SA + kb + tg + 4]);
                a[mf][3] = f2tf32(A[(r + 8) * G1_SA + kb + tg + 4]);
            }
            #pragma unroll
            for (int nf = 0; nf < 4; nf++) {
                int n = n0 + nf * 8 + g;
                b[nf][0] = __float_as_uint(B[(kb + tg) * G1_SB + n]);   // pre-converted
                b[nf][1] = __float_as_uint(B[(kb + tg + 4) * G1_SB + n]);
            }
            #pragma unroll
            for (int mf = 0; mf < 2; mf++)
                #pragma unroll
                for (int nf = 0; nf < 4; nf++)
                    mma_tf32(c[mf][nf], a[mf], b[nf]);
        }
        __syncthreads();
    }

    // ---- epilogue: dinv-prescaled fp16 pairs ----
    #pragma unroll
    for (int mf = 0; mf < 2; mf++) {
        int r0 = row0 + warp_m * 32 + mf * 16 + g;
        int r1 = r0 + 8;
        float d0 = (r0 < M) ? g_dinv[r0] : 0.f;
        float d1 = (r1 < M) ? g_dinv[r1] : 0.f;
        #pragma unroll
        for (int nf = 0; nf < 4; nf++) {
            int col2 = (warp_n * 32 + nf * 8 + tg * 2) >> 1;
            if (r0 < M)
                g_xw1h[(size_t)r0 * (F_HID / 2) + col2] =
                    __floats2half2_rn(d0 * c[mf][nf][0], d0 * c[mf][nf][1]);
            if (r1 < M)
                g_xw1h[(size_t)r1 * (F_HID / 2) + col2] =
                    __floats2half2_rn(d1 * c[mf][nf][2], d1 * c[mf][nf][3]);
        }
    }
}

// ------- agg layer 1 (F=64): pure unweighted sum of prescaled rows ---------
__global__ __launch_bounds__(256) void k_agg1(const float* __restrict__ b1, int N) {
    int lane = threadIdx.x & 31, warp = threadIdx.x >> 5;
    int n = blockIdx.x * 8 + warp;
    if (n >= N) return;
    float bx = b1[lane * 2], by = b1[lane * 2 + 1];

    int start = g_rowptr[n], end = g_rowptr[n + 1];
    float ax = 0.f, ay = 0.f;
    int e = start;
    for (; e + 4 <= end; e += 4) {
        int s0 = g_col[e],     s1 = g_col[e + 1];
        int s2 = g_col[e + 2], s3 = g_col[e + 3];
        float2 v0 = __half22float2(g_xw1h[(size_t)s0 * (F_HID / 2) + lane]);
        float2 v1 = __half22float2(g_xw1h[(size_t)s1 * (F_HID / 2) + lane]);
        float2 v2 = __half22float2(g_xw1h[(size_t)s2 * (F_HID / 2) + lane]);
        float2 v3 = __half22float2(g_xw1h[(size_t)s3 * (F_HID / 2) + lane]);
        ax += v0.x + v1.x + v2.x + v3.x;
        ay += v0.y + v1.y + v2.y + v3.y;
    }
    for (; e < end; e++) {
        int s = g_col[e];
        float2 v = __half22float2(g_xw1h[(size_t)s * (F_HID / 2) + lane]);
        ax += v.x;
        ay += v.y;
    }
    float dn = g_dinv[n];
    float2 sv = __half22float2(g_xw1h[(size_t)n * (F_HID / 2) + lane]);  // = dn*xw[n]
    float ox = fmaxf(dn * (ax + sv.x) + bx, 0.f);
    float oy = fmaxf(dn * (ay + sv.y) + by, 0.f);
    g_hh[(size_t)n * (F_HID / 2) + lane] = __floats2half2_rn(ox, oy);
    if (lane == 0) g_deg[n] = 0;   // restore entry invariant for next replay
}

// ---------------- GEMM2 (tf32 mma): g_hh[M,64] @ W2[64,40], prescaled ------
#define G2_SA 68   // h tile row stride (floats)

__global__ __launch_bounds__(128) void k_gemm2_tf32(const float* __restrict__ W2,
                                                    int M) {
    __shared__ float Af[128 * G2_SA];            // 34.8 KB
    __shared__ float W2s[F_HID * F_OUT];         // 10.2 KB (tf32 bits, k-major)
    int tid = threadIdx.x;
    int lane = tid & 31, warp = tid >> 5;
    int g  = lane >> 2;
    int tg = lane & 3;
    int row0 = blockIdx.x * 128;

    for (int i = tid; i < F_HID * F_OUT; i += 128)
        W2s[i] = __uint_as_float(f2tf32(W2[i]));

    #pragma unroll
    for (int i = 0; i < 8; i++) {
        int idx = tid + i * 128;
        int r = idx >> 3;
        int cq = idx & 7;
        int grow = row0 + r;
        float f[8];
        if (grow < M) {
            uint4 u = *(const uint4*)&g_hh[(size_t)grow * (F_HID / 2) + cq * 4];
            float2 p0 = __half22float2(*(__half2*)&u.x);
            float2 p1 = __half22float2(*(__half2*)&u.y);
            float2 p2 = __half22float2(*(__half2*)&u.z);
            float2 p3 = __half22float2(*(__half2*)&u.w);
            f[0]=p0.x; f[1]=p0.y; f[2]=p1.x; f[3]=p1.y;
            f[4]=p2.x; f[5]=p2.y; f[6]=p3.x; f[7]=p3.y;
        } else {
            #pragma unroll
            for (int j = 0; j < 8; j++) f[j] = 0.f;
        }
        #pragma unroll
        for (int j = 0; j < 8; j++) Af[r * G2_SA + cq * 8 + j] = f[j];
    }
    __syncthreads();

    float c[2][5][4] = {};
    int m0 = warp * 32;
    #pragma unroll
    for (int kb = 0; kb < F_HID; kb += 8) {
        uint32_t a[2][4], b[5][2];
        #pragma unroll
        for (int mf = 0; mf < 2; mf++) {
            int r = m0 + mf * 16 + g;
            a[mf][0] = __float_as_uint(Af[r * G2_SA + kb + tg]);
            a[mf][1] = __float_as_uint(Af[(r + 8) * G2_SA + kb + tg]);
            a[mf][2] = __float_as_uint(Af[r * G2_SA + kb + tg + 4]);
            a[mf][3] = __float_as_uint(Af[(r + 8) * G2_SA + kb + tg + 4]);
        }
        #pragma unroll
        for (int nf = 0; nf < 5; nf++) {
            int n = nf * 8 + g;
            b[nf][0] = __float_as_uint(W2s[(kb + tg) * F_OUT + n]);
            b[nf][1] = __float_as_uint(W2s[(kb + tg + 4) * F_OUT + n]);
        }
        #pragma unroll
        for (int mf = 0; mf < 2; mf++)
            #pragma unroll
            for (int nf = 0; nf < 5; nf++)
                mma_tf32(c[mf][nf], a[mf], b[nf]);
    }

    #pragma unroll
    for (int mf = 0; mf < 2; mf++) {
        int r0 = row0 + m0 + mf * 16 + g;
        int r1 = r0 + 8;
        float d0 = (r0 < M) ? g_dinv[r0] : 0.f;
        float d1 = (r1 < M) ? g_dinv[r1] : 0.f;
        #pragma unroll
        for (int nf = 0; nf < 5; nf++) {
            int col2 = (nf * 8 + tg * 2) >> 1;
            if (r0 < M)
                g_xw2h[(size_t)r0 * (F_OUT / 2) + col2] =
                    __floats2half2_rn(d0 * c[mf][nf][0], d0 * c[mf][nf][1]);
            if (r1 < M)
                g_xw2h[(size_t)r1 * (F_OUT / 2) + col2] =
                    __floats2half2_rn(d1 * c[mf][nf][2], d1 * c[mf][nf][3]);
        }
    }
}

// ------- agg layer 2 (F=40) + bias + fused log_softmax -> d_out ------------
__global__ __launch_bounds__(256) void k_agg2(const float* __restrict__ b2,
                                              float* __restrict__ out, int N,
                                              long long logits_off) {
    int warp = (blockIdx.x * blockDim.x + threadIdx.x) >> 5;
    int lane = threadIdx.x & 31;
    if (warp >= N) return;
    int n = warp;
    bool act = lane < 20;
    int start = g_rowptr[n], end = g_rowptr[n + 1];

    float ax = 0.f, ay = 0.f;
    int e = start;
    for (; e + 4 <= end; e += 4) {
        int s0 = g_col[e],     s1 = g_col[e + 1];
        int s2 = g_col[e + 2], s3 = g_col[e + 3];
        if (act) {
            float2 v0 = __half22float2(g_xw2h[(size_t)s0 * (F_OUT / 2) + lane]);
            float2 v1 = __half22float2(g_xw2h[(size_t)s1 * (F_OUT / 2) + lane]);
            float2 v2 = __half22float2(g_xw2h[(size_t)s2 * (F_OUT / 2) + lane]);
            float2 v3 = __half22float2(g_xw2h[(size_t)s3 * (F_OUT / 2) + lane]);
            ax += v0.x + v1.x + v2.x + v3.x;
            ay += v0.y + v1.y + v2.y + v3.y;
        }
    }
    for (; e < end; e++) {
        int s = g_col[e];
        if (act) {
            float2 v = __half22float2(g_xw2h[(size_t)s * (F_OUT / 2) + lane]);
            ax += v.x;
            ay += v.y;
        }
    }
    float dn = g_dinv[n];
    float o0 = 0.f, o1 = 0.f;
    if (act) {
        float2 sv = __half22float2(g_xw2h[(size_t)n * (F_OUT / 2) + lane]);  // = dn*xw2[n]
        o0 = dn * (ax + sv.x) + b2[lane * 2];
        o1 = dn * (ay + sv.y) + b2[lane * 2 + 1];
    }
    float m = act ? fmaxf(o0, o1) : -3.402823e38f;
    #pragma unroll
    for (int off = 16; off > 0; off >>= 1)
        m = fmaxf(m, __shfl_xor_sync(0xffffffffu, m, off));
    float s = act ? (expf(o0 - m) + expf(o1 - m)) : 0.f;
    #pragma unroll
    for (int off = 16; off > 0; off >>= 1)
        s += __shfl_xor_sync(0xffffffffu, s, off);
    float lse = logf(s) + m;
    if (act) {
        size_t base = (size_t)n * F_OUT + lane * 2;
        out[base]     = o0 - lse;
        out[base + 1] = o1 - lse;
        if (logits_off > 0) {
            out[(size_t)logits_off + base]     = o0;
            out[(size_t)logits_off + base + 1] = o1;
        }
    }
}

// ---------------------------------------------------------------------------
extern "C" void kernel_launch(void* const* d_in, const int* in_sizes, int n_in,
                              void* d_out, int out_size) {
    const float* x  = (const float*)d_in[0];
    const int*   ei = (const int*)d_in[1];     // int32 (JAX x64 disabled)
    const float* W1 = (const float*)d_in[2];
    const float* b1 = (const float*)d_in[3];
    const float* W2 = (const float*)d_in[4];
    const float* b2 = (const float*)d_in[5];
    float* out = (float*)d_out;

    int N = in_sizes[0] / F_IN;    // 100000
    int E = in_sizes[1] / 2;       // 1600000
    int NB = (N + 1023) / 1024;    // 98 scan blocks

    long long logits_off = ((long long)out_size >= 2LL * N * F_OUT)
                         ? (long long)N * F_OUT : 0;

    // not a stream op; idempotent and legal during graph capture
    cudaFuncSetAttribute(k_gemm1_tf32,
                         cudaFuncAttributeMaxDynamicSharedMemorySize,
                         G1_SMEM_BYTES);

    // graph preprocessing (g_deg == 0 at entry: module init / agg1 re-zero)
    k_deg<<<(E + 255) / 256, 256>>>(ei, W1, E);
    k_scan_blocks<<<NB, 1024>>>(N);
    k_scan_add<<<NB, 1024>>>(N, E, NB);
    k_fill_col<<<(E + 255) / 256, 256>>>(ei, E);

    // layer 1
    k_gemm1_tf32<<<(N + G1_BM - 1) / G1_BM, 256, G1_SMEM_BYTES>>>(x, N);
    k_agg1<<<(N + 7) / 8, 256>>>(b1, N);

    // layer 2
    k_gemm2_tf32<<<(N + 127) / 128, 128>>>(W2, N);
    k_agg2<<<(N * 32 + 255) / 256, 256>>>(b2, out, N, logits_off);
}